// round 3
// baseline (speedup 1.0000x reference)
#include <cuda_runtime.h>

// SpatialGRU wavefront: 64 persistent CTAs (one per column r), 256 threads.
// CTA r computes cells (l, r), l = 0..63, spinning on CTA r-1's flag.

namespace cfg {
constexpr int B = 64, C = 16, L = 64, R = 64, U = 64;
constexpr int D = 208, NR = 192, NRZ = 448;
// smem floats
constexpr int SM_HT = 0;          // 64x64
constexpr int SM_P0 = 4096;       // 64x64 ping
constexpr int SM_P1 = 8192;       // 64x64 pong
constexpr int SM_X  = 12288;      // 64x16
constexpr int SM_RR = 13312;      // 64x192 (rr * hu)
constexpr int SM_Z  = 25600;      // 64x256 (gate pre-acts)
constexpr int SM_FLOATS = 41984;
constexpr int SM_BYTES = SM_FLOATS * 4;   // 167936
}

__device__ __align__(16) float g_x[cfg::L * cfg::R * cfg::B * cfg::C];
__device__ __align__(16) float g_h[cfg::L * cfg::R * cfg::B * cfg::U];
__device__ __align__(16) float g_wtrz[cfg::D * cfg::NRZ];  // [k][n], n<192: wr, else wz
__device__ __align__(16) float g_wt2[cfg::D * cfg::U];     // [k][n], k<192: U_w, else wij
__device__ int g_flag[cfg::R];

// ---------------- helpers ----------------------------------------------------
__device__ __forceinline__ unsigned long long f2_pack(float lo, float hi) {
    unsigned long long d;
    asm("mov.b64 %0, {%1, %2};" : "=l"(d) : "f"(lo), "f"(hi));
    return d;
}
__device__ __forceinline__ unsigned long long f2_dup(float a) {
    unsigned long long d;
    asm("mov.b64 %0, {%1, %1};" : "=l"(d) : "f"(a));
    return d;
}
__device__ __forceinline__ float2 f2_unpack(unsigned long long v) {
    float2 r;
    asm("mov.b64 {%0, %1}, %2;" : "=f"(r.x), "=f"(r.y) : "l"(v));
    return r;
}
__device__ __forceinline__ unsigned long long f2_fma(unsigned long long a,
                                                     unsigned long long b,
                                                     unsigned long long c) {
    unsigned long long d;
    asm("fma.rn.f32x2 %0, %1, %2, %3;" : "=l"(d) : "l"(a), "l"(b), "l"(c));
    return d;
}
__device__ __forceinline__ int ld_acq(const int* p) {
    int v;
    asm volatile("ld.global.acquire.gpu.b32 %0, [%1];" : "=r"(v) : "l"(p) : "memory");
    return v;
}
__device__ __forceinline__ void st_rel(int* p, int v) {
    asm volatile("st.global.release.gpu.b32 [%0], %1;" :: "l"(p), "r"(v) : "memory");
}
__device__ __forceinline__ float fsigmoid(float x) { return 1.f / (1.f + __expf(-x)); }

// ---------------- setup kernels ----------------------------------------------
// inputs viewed [bc=1024][lr=4096]  ->  g_x [lr][bc]
__global__ void k_transpose(const float* __restrict__ in) {
    __shared__ float tile[32][33];
    int lr0 = blockIdx.x * 32, bc0 = blockIdx.y * 32;
    int tx = threadIdx.x, ty = threadIdx.y;
#pragma unroll
    for (int j = 0; j < 4; ++j)
        tile[ty + 8 * j][tx] = in[(size_t)(bc0 + ty + 8 * j) * 4096 + lr0 + tx];
    __syncthreads();
#pragma unroll
    for (int j = 0; j < 4; ++j)
        g_x[(size_t)(lr0 + ty + 8 * j) * 1024 + bc0 + tx] = tile[tx][ty + 8 * j];
}

__global__ void k_prep(const float* __restrict__ wr_w, const float* __restrict__ wz_w,
                       const float* __restrict__ wij_w, const float* __restrict__ U_w) {
    using namespace cfg;
    int idx = blockIdx.x * blockDim.x + threadIdx.x;
    const int tot1 = D * NRZ;  // 93184
    if (idx < tot1) {
        int k = idx / NRZ, n = idx % NRZ;
        g_wtrz[idx] = (n < NR) ? wr_w[n * D + k] : wz_w[(n - NR) * D + k];
    } else if (idx - tot1 < D * U) {
        int i2 = idx - tot1;
        int k = i2 / U, n = i2 % U;
        g_wt2[i2] = (k < NR) ? U_w[n * NR + k] : wij_w[n * C + (k - NR)];
    }
    if (idx < R) g_flag[idx] = 0;
}

// ---------------- GEMM segment: 4 rows x 4 cols per thread, f32x2 ------------
template <int RS, int KLEN>
__device__ __forceinline__ void gemm_seg(const float* __restrict__ A,
                                         const float* __restrict__ Wc, int wstride,
                                         int ty, unsigned long long acc0[4],
                                         unsigned long long acc1[4]) {
#pragma unroll 2
    for (int k = 0; k < KLEN; k += 4) {
        float avr[4][4];
#pragma unroll
        for (int i = 0; i < 4; ++i)
            *reinterpret_cast<float4*>(avr[i]) =
                *reinterpret_cast<const float4*>(&A[(ty + 16 * i) * RS + k]);
#pragma unroll
        for (int kk = 0; kk < 4; ++kk) {
            ulonglong2 w = *reinterpret_cast<const ulonglong2*>(Wc + (k + kk) * wstride);
#pragma unroll
            for (int i = 0; i < 4; ++i) {
                unsigned long long d = f2_dup(avr[i][kk]);
                acc0[i] = f2_fma(d, w.x, acc0[i]);
                acc1[i] = f2_fma(d, w.y, acc1[i]);
            }
        }
    }
}

// ---------------- wavefront kernel -------------------------------------------
__global__ __launch_bounds__(256, 1) void k_wave(const float* __restrict__ wr_b,
                                                 const float* __restrict__ wz_b,
                                                 const float* __restrict__ wij_b,
                                                 float* __restrict__ out) {
    using namespace cfg;
    extern __shared__ float sm[];
    float* sHT = sm + SM_HT;
    float* sX  = sm + SM_X;
    float* sRR = sm + SM_RR;
    float* sZ  = sm + SM_Z;

    const int tid = threadIdx.x;
    const int tx = tid & 15, ty = tid >> 4;
    const int lc0 = 4 * tx;
    const int r = blockIdx.x;

    for (int i = tid; i < 3 * 4096; i += 256) sm[i] = 0.f;  // HT, P0, P1 = 0
    __syncthreads();

#pragma unroll 1
    for (int l = 0; l < L; ++l) {
        float* sHL = sm + ((l & 1) ? SM_P1 : SM_P0);  // h(l, r-1)
        float* sHD = sm + ((l & 1) ? SM_P0 : SM_P1);  // h(l-1, r-1)

        if (r > 0) {
            if (tid == 0) {
                while (ld_acq(&g_flag[r - 1]) < l + 1) __nanosleep(64);
            }
            __syncthreads();
            const float4* src =
                reinterpret_cast<const float4*>(g_h + (size_t)(l * R + (r - 1)) * 4096);
            float4* dst = reinterpret_cast<float4*>(sHL);
            for (int i = tid; i < 1024; i += 256) dst[i] = src[i];
        }
        reinterpret_cast<float4*>(sX)[tid] =
            reinterpret_cast<const float4*>(g_x + (size_t)(l * R + r) * 1024)[tid];
        __syncthreads();

        // ---- GEMM1: [HT|HL|HD|X] @ Wrz  (7 chunks of 64 cols) ----
#pragma unroll 1
        for (int c = 0; c < 7; ++c) {
            const float* bias = (c < 3) ? (wr_b + c * 64) : (wz_b + (c - 3) * 64);
            float4 b4 = *reinterpret_cast<const float4*>(bias + lc0);
            unsigned long long acc0[4], acc1[4];
            unsigned long long i01 = f2_pack(b4.x, b4.y), i23 = f2_pack(b4.z, b4.w);
#pragma unroll
            for (int i = 0; i < 4; ++i) { acc0[i] = i01; acc1[i] = i23; }

            const float* Wc = g_wtrz + c * 64 + lc0;
            gemm_seg<64, 64>(sHT, Wc, NRZ, ty, acc0, acc1);
            gemm_seg<64, 64>(sHL, Wc + 64 * NRZ, NRZ, ty, acc0, acc1);
            gemm_seg<64, 64>(sHD, Wc + 128 * NRZ, NRZ, ty, acc0, acc1);
            gemm_seg<16, 16>(sX, Wc + 192 * NRZ, NRZ, ty, acc0, acc1);

            if (c < 3) {
                // rr = sigmoid(pre); store rr*hu, hu order: [h_left, h_top, h_diag]
                const float* HU = (c == 0) ? sHL : (c == 1) ? sHT : sHD;
#pragma unroll
                for (int i = 0; i < 4; ++i) {
                    int row = ty + 16 * i;
                    float2 v01 = f2_unpack(acc0[i]), v23 = f2_unpack(acc1[i]);
                    float4 hu4 = *reinterpret_cast<const float4*>(&HU[row * 64 + lc0]);
                    float4 o;
                    o.x = hu4.x * fsigmoid(v01.x);
                    o.y = hu4.y * fsigmoid(v01.y);
                    o.z = hu4.z * fsigmoid(v23.x);
                    o.w = hu4.w * fsigmoid(v23.y);
                    *reinterpret_cast<float4*>(&sRR[row * NR + c * 64 + lc0]) = o;
                }
            } else {
#pragma unroll
                for (int i = 0; i < 4; ++i) {
                    int row = ty + 16 * i;
                    float2 v01 = f2_unpack(acc0[i]), v23 = f2_unpack(acc1[i]);
                    float4 o = {v01.x, v01.y, v23.x, v23.y};
                    *reinterpret_cast<float4*>(&sZ[row * 256 + (c - 3) * 64 + lc0]) = o;
                }
            }
        }
        __syncthreads();

        // ---- GEMM2: [rr*hu | x] @ [U_w | wij_w]^T, then gates + h ----
        {
            float4 b4 = *reinterpret_cast<const float4*>(wij_b + lc0);
            unsigned long long acc0[4], acc1[4];
            unsigned long long i01 = f2_pack(b4.x, b4.y), i23 = f2_pack(b4.z, b4.w);
#pragma unroll
            for (int i = 0; i < 4; ++i) { acc0[i] = i01; acc1[i] = i23; }

            const float* Wc = g_wt2 + lc0;
            gemm_seg<192, 192>(sRR, Wc, U, ty, acc0, acc1);
            gemm_seg<16, 16>(sX, Wc + 192 * U, U, ty, acc0, acc1);

#pragma unroll
            for (int i = 0; i < 4; ++i) {
                int row = ty + 16 * i;
                float2 v01 = f2_unpack(acc0[i]), v23 = f2_unpack(acc1[i]);
                float hn[4] = {tanhf(v01.x), tanhf(v01.y), tanhf(v23.x), tanhf(v23.y)};
                const float* zr = sZ + row * 256 + lc0;
                float4 zi4 = *reinterpret_cast<const float4*>(zr);
                float4 zl4 = *reinterpret_cast<const float4*>(zr + 64);
                float4 zt4 = *reinterpret_cast<const float4*>(zr + 128);
                float4 zd4 = *reinterpret_cast<const float4*>(zr + 192);
                float4 hl4 = *reinterpret_cast<const float4*>(&sHL[row * 64 + lc0]);
                float4 ht4 = *reinterpret_cast<const float4*>(&sHT[row * 64 + lc0]);
                float4 hd4 = *reinterpret_cast<const float4*>(&sHD[row * 64 + lc0]);
                float zi[4] = {zi4.x, zi4.y, zi4.z, zi4.w};
                float zl[4] = {zl4.x, zl4.y, zl4.z, zl4.w};
                float zt[4] = {zt4.x, zt4.y, zt4.z, zt4.w};
                float zd[4] = {zd4.x, zd4.y, zd4.z, zd4.w};
                float hl[4] = {hl4.x, hl4.y, hl4.z, hl4.w};
                float ht[4] = {ht4.x, ht4.y, ht4.z, ht4.w};
                float hd[4] = {hd4.x, hd4.y, hd4.z, hd4.w};
                float h[4];
#pragma unroll
                for (int j = 0; j < 4; ++j) {
                    float m = fmaxf(fmaxf(zi[j], zl[j]), fmaxf(zt[j], zd[j]));
                    float ei = __expf(zi[j] - m), el = __expf(zl[j] - m);
                    float et = __expf(zt[j] - m), ed = __expf(zd[j] - m);
                    float inv = 1.f / (ei + el + et + ed);
                    h[j] = (el * hl[j] + et * ht[j] + ed * hd[j] + ei * hn[j]) * inv;
                }
                float4 h4 = {h[0], h[1], h[2], h[3]};
                *reinterpret_cast<float4*>(&sHT[row * 64 + lc0]) = h4;
                *reinterpret_cast<float4*>(
                    g_h + ((size_t)(l * R + r) * 64 + row) * 64 + lc0) = h4;
                if (l == L - 1 && r == R - 1)
                    *reinterpret_cast<float4*>(out + row * 64 + lc0) = h4;
            }
        }
        __threadfence();
        __syncthreads();
        if (tid == 0) st_rel(&g_flag[r], l + 1);
    }
}

// ---------------- launch ------------------------------------------------------
extern "C" void kernel_launch(void* const* d_in, const int* in_sizes, int n_in,
                              void* d_out, int out_size) {
    const float* inputs = (const float*)d_in[0];
    const float* wr_w = (const float*)d_in[1];
    const float* wr_b = (const float*)d_in[2];
    const float* wz_w = (const float*)d_in[3];
    const float* wz_b = (const float*)d_in[4];
    const float* wij_w = (const float*)d_in[5];
    const float* wij_b = (const float*)d_in[6];
    const float* U_w = (const float*)d_in[7];
    float* out = (float*)d_out;

    cudaFuncSetAttribute(k_wave, cudaFuncAttributeMaxDynamicSharedMemorySize,
                         cfg::SM_BYTES);

    dim3 tt(32, 8), tb(4096 / 32, 1024 / 32);
    k_transpose<<<tb, tt>>>(inputs);
    k_prep<<<416, 256>>>(wr_w, wz_w, wij_w, U_w);
    k_wave<<<cfg::R, 256, cfg::SM_BYTES>>>(wr_b, wz_b, wij_b, out);
}

// round 4
// speedup vs baseline: 1.2135x; 1.2135x over previous
#include <cuda_runtime.h>

// SpatialGRU wavefront v2: 64 persistent CTAs (one per column r), 448 threads.
// x-projections + biases precomputed into g_s; wavefront does K=192 GEMMs only.

namespace cfg {
constexpr int SM_RR = 12288;   // after HT(4096), P0, P1
constexpr int SM_Z  = 24576;
constexpr int SM_FLOATS = 40960;
constexpr int SM_BYTES = SM_FLOATS * 4;   // 163840
}

__device__ __align__(16) float g_s[(size_t)4096 * 64 * 512];   // [cell][b][512]
__device__ __align__(16) float g_h[(size_t)4096 * 64 * 64];    // [cell][b][u]
__device__ __align__(16) float g_wtrz[192 * 448];              // [k][n]
__device__ __align__(16) float g_wt2[192 * 64];                // [k][n] (U_w^T)
__device__ __align__(16) float g_wx[16 * 512];                 // [c][n]
__device__ __align__(16) float g_bias[512];
__device__ int g_flag[64];

// ---------------- helpers ----------------------------------------------------
__device__ __forceinline__ unsigned long long f2_pack(float lo, float hi) {
    unsigned long long d;
    asm("mov.b64 %0, {%1, %2};" : "=l"(d) : "f"(lo), "f"(hi));
    return d;
}
__device__ __forceinline__ unsigned long long f2_dup(float a) {
    unsigned long long d;
    asm("mov.b64 %0, {%1, %1};" : "=l"(d) : "f"(a));
    return d;
}
__device__ __forceinline__ float2 f2_unpack(unsigned long long v) {
    float2 r;
    asm("mov.b64 {%0, %1}, %2;" : "=f"(r.x), "=f"(r.y) : "l"(v));
    return r;
}
__device__ __forceinline__ unsigned long long f2_fma(unsigned long long a,
                                                     unsigned long long b,
                                                     unsigned long long c) {
    unsigned long long d;
    asm("fma.rn.f32x2 %0, %1, %2, %3;" : "=l"(d) : "l"(a), "l"(b), "l"(c));
    return d;
}
__device__ __forceinline__ int ld_acq(const int* p) {
    int v;
    asm volatile("ld.global.acquire.gpu.b32 %0, [%1];" : "=r"(v) : "l"(p) : "memory");
    return v;
}
__device__ __forceinline__ void st_rel(int* p, int v) {
    asm volatile("st.global.release.gpu.b32 [%0], %1;" :: "l"(p), "r"(v) : "memory");
}
__device__ __forceinline__ float fsigmoid(float x) { return 1.f / (1.f + __expf(-x)); }

// ---------------- setup ------------------------------------------------------
__global__ void k_nop() {}

__global__ void k_prep(const float* __restrict__ wr_w, const float* __restrict__ wz_w,
                       const float* __restrict__ wij_w, const float* __restrict__ U_w,
                       const float* __restrict__ wr_b, const float* __restrict__ wz_b,
                       const float* __restrict__ wij_b) {
    int idx = blockIdx.x * 256 + threadIdx.x;   // 418*256 = 107008 exact
    const int T1 = 192 * 448, T2 = T1 + 192 * 64, T3 = T2 + 16 * 512;
    if (idx < T1) {
        int k = idx / 448, n = idx % 448;
        g_wtrz[idx] = (n < 192) ? wr_w[n * 208 + k] : wz_w[(n - 192) * 208 + k];
    } else if (idx < T2) {
        int i2 = idx - T1;
        int k = i2 / 64, n = i2 % 64;
        g_wt2[i2] = U_w[n * 192 + k];
    } else if (idx < T3) {
        int i2 = idx - T2;
        int c = i2 / 512, n = i2 % 512;
        g_wx[i2] = (n < 192)   ? wr_w[n * 208 + 192 + c]
                 : (n < 448) ? wz_w[(n - 192) * 208 + 192 + c]
                             : wij_w[(n - 448) * 16 + c];
    } else {
        int n = idx - T3;
        g_bias[n] = (n < 192) ? wr_b[n] : (n < 448) ? wz_b[n - 192] : wij_b[n - 448];
    }
    if (idx < 64) g_flag[idx] = 0;
}

// g_s[cell][row][col] = sum_c x[row][c] * Wx[c][col] + bias[col]
__global__ __launch_bounds__(256) void k_sxz(const float* __restrict__ inputs) {
    __shared__ float sW[16 * 512];
    __shared__ float sb[512];
    __shared__ float sx[64 * 16];
    const int cell = blockIdx.x;
    const int tid = threadIdx.x;
    for (int i = tid; i < 8192; i += 256) sW[i] = g_wx[i];
    for (int i = tid; i < 512; i += 256) sb[i] = g_bias[i];
    for (int i = tid; i < 1024; i += 256) sx[i] = inputs[(size_t)i * 4096 + cell];
    __syncthreads();
    const int ryq = tid >> 4, cx = tid & 15;
    const int row0 = ryq * 4;
    float* outp = g_s + (size_t)cell * 64 * 512;
#pragma unroll 1
    for (int p = 0; p < 4; ++p) {
        const int col0 = p * 128 + cx * 8;
        unsigned long long acc[4][4];
        {
            float4 b0 = *reinterpret_cast<const float4*>(&sb[col0]);
            float4 b1 = *reinterpret_cast<const float4*>(&sb[col0 + 4]);
            unsigned long long p0 = f2_pack(b0.x, b0.y), p1 = f2_pack(b0.z, b0.w);
            unsigned long long p2 = f2_pack(b1.x, b1.y), p3 = f2_pack(b1.z, b1.w);
#pragma unroll
            for (int i = 0; i < 4; ++i) {
                acc[i][0] = p0; acc[i][1] = p1; acc[i][2] = p2; acc[i][3] = p3;
            }
        }
#pragma unroll
        for (int k = 0; k < 16; k += 4) {
            float4 a[4];
#pragma unroll
            for (int i = 0; i < 4; ++i)
                a[i] = *reinterpret_cast<const float4*>(&sx[(row0 + i) * 16 + k]);
#pragma unroll
            for (int kk = 0; kk < 4; ++kk) {
                ulonglong2 w0 = *reinterpret_cast<const ulonglong2*>(sW + (k + kk) * 512 + col0);
                ulonglong2 w1 = *reinterpret_cast<const ulonglong2*>(sW + (k + kk) * 512 + col0 + 4);
#pragma unroll
                for (int i = 0; i < 4; ++i) {
                    unsigned long long d = f2_dup(reinterpret_cast<const float*>(&a[i])[kk]);
                    acc[i][0] = f2_fma(d, w0.x, acc[i][0]);
                    acc[i][1] = f2_fma(d, w0.y, acc[i][1]);
                    acc[i][2] = f2_fma(d, w1.x, acc[i][2]);
                    acc[i][3] = f2_fma(d, w1.y, acc[i][3]);
                }
            }
        }
#pragma unroll
        for (int i = 0; i < 4; ++i) {
            float2 u0 = f2_unpack(acc[i][0]), u1 = f2_unpack(acc[i][1]);
            float2 u2 = f2_unpack(acc[i][2]), u3 = f2_unpack(acc[i][3]);
            float4 o0 = {u0.x, u0.y, u1.x, u1.y};
            float4 o1 = {u2.x, u2.y, u3.x, u3.y};
            *reinterpret_cast<float4*>(&outp[(row0 + i) * 512 + col0]) = o0;
            *reinterpret_cast<float4*>(&outp[(row0 + i) * 512 + col0 + 4]) = o1;
        }
    }
}

// ---------------- wavefront GEMM pieces --------------------------------------
// 4 rows x 8 cols, K=64 segment, A(64-wide) in smem, W in global [k][448]
__device__ __forceinline__ void gemm8_seg(const float* __restrict__ A, int row0,
                                          const float* __restrict__ Wc,
                                          unsigned long long acc[4][4]) {
#pragma unroll 4
    for (int k = 0; k < 64; k += 4) {
        float4 a[4];
#pragma unroll
        for (int i = 0; i < 4; ++i)
            a[i] = *reinterpret_cast<const float4*>(&A[(row0 + i) * 64 + k]);
#pragma unroll
        for (int kk = 0; kk < 4; ++kk) {
            ulonglong2 w0 = *reinterpret_cast<const ulonglong2*>(Wc + (k + kk) * 448);
            ulonglong2 w1 = *reinterpret_cast<const ulonglong2*>(Wc + (k + kk) * 448 + 4);
#pragma unroll
            for (int i = 0; i < 4; ++i) {
                unsigned long long d = f2_dup(reinterpret_cast<const float*>(&a[i])[kk]);
                acc[i][0] = f2_fma(d, w0.x, acc[i][0]);
                acc[i][1] = f2_fma(d, w0.y, acc[i][1]);
                acc[i][2] = f2_fma(d, w1.x, acc[i][2]);
                acc[i][3] = f2_fma(d, w1.y, acc[i][3]);
            }
        }
    }
}

// 4 rows (ty+16i) x 4 cols, K=192, A(192-wide) smem, W [k][64] global (GEMM2)
__device__ __forceinline__ void gemm2_seg(const float* __restrict__ A,
                                          const float* __restrict__ Wc, int ty,
                                          unsigned long long acc0[4],
                                          unsigned long long acc1[4]) {
#pragma unroll 4
    for (int k = 0; k < 192; k += 4) {
        float avr[4][4];
#pragma unroll
        for (int i = 0; i < 4; ++i)
            *reinterpret_cast<float4*>(avr[i]) =
                *reinterpret_cast<const float4*>(&A[(ty + 16 * i) * 192 + k]);
#pragma unroll
        for (int kk = 0; kk < 4; ++kk) {
            ulonglong2 w = *reinterpret_cast<const ulonglong2*>(Wc + (k + kk) * 64);
#pragma unroll
            for (int i = 0; i < 4; ++i) {
                unsigned long long d = f2_dup(avr[i][kk]);
                acc0[i] = f2_fma(d, w.x, acc0[i]);
                acc1[i] = f2_fma(d, w.y, acc1[i]);
            }
        }
    }
}

// ---------------- wavefront kernel -------------------------------------------
__global__ __launch_bounds__(448, 1) void k_wave(float* __restrict__ out) {
    extern __shared__ float sm[];
    float* sHT = sm;
    float* sRR = sm + cfg::SM_RR;
    float* sZ  = sm + cfg::SM_Z;

    const int tid = threadIdx.x;
    const int ry = tid / 28, cg = tid % 28;   // 16 x 28
    const int row0 = ry * 4;
    const int tx2 = tid & 15, ty2 = tid >> 4;
    const int lc0 = 4 * tx2;
    const int r = blockIdx.x;

    for (int i = tid; i < 3 * 4096; i += 448) sm[i] = 0.f;
    __syncthreads();

#pragma unroll 1
    for (int l = 0; l < 64; ++l) {
        float* sHL = sm + ((l & 1) ? 8192 : 4096);
        float* sHD = sm + ((l & 1) ? 4096 : 8192);

        if (r > 0) {
            if (tid == 0) {
                while (ld_acq(&g_flag[r - 1]) < l + 1) __nanosleep(64);
            }
            __syncthreads();
            const float4* src =
                reinterpret_cast<const float4*>(g_h + (size_t)(l * 64 + (r - 1)) * 4096);
            float4* dst = reinterpret_cast<float4*>(sHL);
            for (int i = tid; i < 1024; i += 448) dst[i] = src[i];
            __syncthreads();
        }

        const size_t cellbase = (size_t)(l * 64 + r) * 64 * 512;

        // ---- GEMM1: [HT|HL|HD] @ Wrz + g_s  (2 passes of 224 cols) ----
#pragma unroll 1
        for (int p = 0; p < 2; ++p) {
            const int col0 = p * 224 + cg * 8;
            const int blk = col0 >> 6, off = col0 & 63;
            unsigned long long acc[4][4];
            const float* sp = g_s + cellbase + col0;
#pragma unroll
            for (int i = 0; i < 4; ++i) {
                float4 s0 = *reinterpret_cast<const float4*>(sp + (row0 + i) * 512);
                float4 s1 = *reinterpret_cast<const float4*>(sp + (row0 + i) * 512 + 4);
                acc[i][0] = f2_pack(s0.x, s0.y); acc[i][1] = f2_pack(s0.z, s0.w);
                acc[i][2] = f2_pack(s1.x, s1.y); acc[i][3] = f2_pack(s1.z, s1.w);
            }
            const float* Wc = g_wtrz + col0;
            gemm8_seg(sHT, row0, Wc, acc);
            gemm8_seg(sHL, row0, Wc + 64 * 448, acc);
            gemm8_seg(sHD, row0, Wc + 128 * 448, acc);

            if (blk < 3) {
                const float* HU = (blk == 0) ? sHL : (blk == 1) ? sHT : sHD;
#pragma unroll
                for (int i = 0; i < 4; ++i) {
                    int row = row0 + i;
                    float2 u0 = f2_unpack(acc[i][0]), u1 = f2_unpack(acc[i][1]);
                    float2 u2 = f2_unpack(acc[i][2]), u3 = f2_unpack(acc[i][3]);
                    float4 h0 = *reinterpret_cast<const float4*>(&HU[row * 64 + off]);
                    float4 h1 = *reinterpret_cast<const float4*>(&HU[row * 64 + off + 4]);
                    float4 o0 = {h0.x * fsigmoid(u0.x), h0.y * fsigmoid(u0.y),
                                 h0.z * fsigmoid(u1.x), h0.w * fsigmoid(u1.y)};
                    float4 o1 = {h1.x * fsigmoid(u2.x), h1.y * fsigmoid(u2.y),
                                 h1.z * fsigmoid(u3.x), h1.w * fsigmoid(u3.y)};
                    *reinterpret_cast<float4*>(&sRR[row * 192 + blk * 64 + off]) = o0;
                    *reinterpret_cast<float4*>(&sRR[row * 192 + blk * 64 + off + 4]) = o1;
                }
            } else {
#pragma unroll
                for (int i = 0; i < 4; ++i) {
                    int row = row0 + i;
                    float2 u0 = f2_unpack(acc[i][0]), u1 = f2_unpack(acc[i][1]);
                    float2 u2 = f2_unpack(acc[i][2]), u3 = f2_unpack(acc[i][3]);
                    float4 o0 = {u0.x, u0.y, u1.x, u1.y};
                    float4 o1 = {u2.x, u2.y, u3.x, u3.y};
                    *reinterpret_cast<float4*>(&sZ[row * 256 + (blk - 3) * 64 + off]) = o0;
                    *reinterpret_cast<float4*>(&sZ[row * 256 + (blk - 3) * 64 + off + 4]) = o1;
                }
            }
        }
        __syncthreads();

        // ---- GEMM2 (tid < 256): rr*hu @ U_w^T + g_s[:,448:], then gates ----
        if (tid < 256) {
            unsigned long long acc0[4], acc1[4];
#pragma unroll
            for (int i = 0; i < 4; ++i) {
                int row = ty2 + 16 * i;
                float4 s = *reinterpret_cast<const float4*>(
                    g_s + cellbase + (size_t)row * 512 + 448 + lc0);
                acc0[i] = f2_pack(s.x, s.y);
                acc1[i] = f2_pack(s.z, s.w);
            }
            gemm2_seg(sRR, g_wt2 + lc0, ty2, acc0, acc1);

#pragma unroll
            for (int i = 0; i < 4; ++i) {
                int row = ty2 + 16 * i;
                float2 v01 = f2_unpack(acc0[i]), v23 = f2_unpack(acc1[i]);
                float hn[4] = {tanhf(v01.x), tanhf(v01.y), tanhf(v23.x), tanhf(v23.y)};
                const float* zr = sZ + row * 256 + lc0;
                float4 zi4 = *reinterpret_cast<const float4*>(zr);
                float4 zl4 = *reinterpret_cast<const float4*>(zr + 64);
                float4 zt4 = *reinterpret_cast<const float4*>(zr + 128);
                float4 zd4 = *reinterpret_cast<const float4*>(zr + 192);
                float4 hl4 = *reinterpret_cast<const float4*>(&sHL[row * 64 + lc0]);
                float4 ht4 = *reinterpret_cast<const float4*>(&sHT[row * 64 + lc0]);
                float4 hd4 = *reinterpret_cast<const float4*>(&sHD[row * 64 + lc0]);
                float zi[4] = {zi4.x, zi4.y, zi4.z, zi4.w};
                float zl[4] = {zl4.x, zl4.y, zl4.z, zl4.w};
                float zt[4] = {zt4.x, zt4.y, zt4.z, zt4.w};
                float zd[4] = {zd4.x, zd4.y, zd4.z, zd4.w};
                float hl[4] = {hl4.x, hl4.y, hl4.z, hl4.w};
                float ht[4] = {ht4.x, ht4.y, ht4.z, ht4.w};
                float hd[4] = {hd4.x, hd4.y, hd4.z, hd4.w};
                float h[4];
#pragma unroll
                for (int j = 0; j < 4; ++j) {
                    float m = fmaxf(fmaxf(zi[j], zl[j]), fmaxf(zt[j], zd[j]));
                    float ei = __expf(zi[j] - m), el = __expf(zl[j] - m);
                    float et = __expf(zt[j] - m), ed = __expf(zd[j] - m);
                    float inv = 1.f / (ei + el + et + ed);
                    h[j] = (el * hl[j] + et * ht[j] + ed * hd[j] + ei * hn[j]) * inv;
                }
                float4 h4 = {h[0], h[1], h[2], h[3]};
                *reinterpret_cast<float4*>(&sHT[row * 64 + lc0]) = h4;
                if (r < 63)
                    *reinterpret_cast<float4*>(
                        g_h + ((size_t)(l * 64 + r) * 64 + row) * 64 + lc0) = h4;
                if (l == 63 && r == 63)
                    *reinterpret_cast<float4*>(out + row * 64 + lc0) = h4;
            }
        }
        __threadfence();
        __syncthreads();
        if (tid == 0) st_rel(&g_flag[r], l + 1);
    }
}

// ---------------- launch ------------------------------------------------------
extern "C" void kernel_launch(void* const* d_in, const int* in_sizes, int n_in,
                              void* d_out, int out_size) {
    const float* inputs = (const float*)d_in[0];
    const float* wr_w = (const float*)d_in[1];
    const float* wr_b = (const float*)d_in[2];
    const float* wz_w = (const float*)d_in[3];
    const float* wz_b = (const float*)d_in[4];
    const float* wij_w = (const float*)d_in[5];
    const float* wij_b = (const float*)d_in[6];
    const float* U_w = (const float*)d_in[7];
    float* out = (float*)d_out;

    cudaFuncSetAttribute(k_wave, cudaFuncAttributeMaxDynamicSharedMemorySize,
                         cfg::SM_BYTES);

    k_nop<<<1, 1>>>();
    k_prep<<<418, 256>>>(wr_w, wz_w, wij_w, U_w, wr_b, wz_b, wij_b);
    k_sxz<<<4096, 256>>>(inputs);
    k_wave<<<64, 448, cfg::SM_BYTES>>>(out);
}

// round 6
// speedup vs baseline: 1.2975x; 1.0692x over previous
#include <cuda_runtime.h>

// SpatialGRU wavefront v3: 64 persistent CTAs x 896 threads.
// GEMM1 thread tile 8 rows x 4 cols, column-fast lane mapping so W loads are
// line-contiguous (4 L1 wavefronts per LDG.128 instead of 7).

namespace cfg {
constexpr int SM_RR = 12288;   // after HT(4096), P0(4096), P1(4096)
constexpr int SM_Z  = 24576;
constexpr int SM_FLOATS = 40960;
constexpr int SM_BYTES = SM_FLOATS * 4;   // 163840
}

__device__ __align__(16) float g_s[(size_t)4096 * 64 * 512];   // [cell][b][512]
__device__ __align__(16) float g_h[(size_t)4096 * 64 * 64];    // [cell][b][u]
__device__ __align__(16) float g_wtrz[192 * 448];              // [k][n]
__device__ __align__(16) float g_wt2[192 * 64];                // [k][n] (U_w^T)
__device__ __align__(16) float g_wx[16 * 512];                 // [c][n]
__device__ __align__(16) float g_bias[512];
__device__ int g_flag[64];

// ---------------- helpers ----------------------------------------------------
__device__ __forceinline__ unsigned long long f2_pack(float lo, float hi) {
    unsigned long long d;
    asm("mov.b64 %0, {%1, %2};" : "=l"(d) : "f"(lo), "f"(hi));
    return d;
}
__device__ __forceinline__ unsigned long long f2_dup(float a) {
    unsigned long long d;
    asm("mov.b64 %0, {%1, %1};" : "=l"(d) : "f"(a));
    return d;
}
__device__ __forceinline__ float2 f2_unpack(unsigned long long v) {
    float2 r;
    asm("mov.b64 {%0, %1}, %2;" : "=f"(r.x), "=f"(r.y) : "l"(v));
    return r;
}
__device__ __forceinline__ unsigned long long f2_fma(unsigned long long a,
                                                     unsigned long long b,
                                                     unsigned long long c) {
    unsigned long long d;
    asm("fma.rn.f32x2 %0, %1, %2, %3;" : "=l"(d) : "l"(a), "l"(b), "l"(c));
    return d;
}
__device__ __forceinline__ int ld_acq(const int* p) {
    int v;
    asm volatile("ld.global.acquire.gpu.b32 %0, [%1];" : "=r"(v) : "l"(p) : "memory");
    return v;
}
__device__ __forceinline__ void st_rel(int* p, int v) {
    asm volatile("st.global.release.gpu.b32 [%0], %1;" :: "l"(p), "r"(v) : "memory");
}
__device__ __forceinline__ float fsigmoid(float x) { return 1.f / (1.f + __expf(-x)); }

// ---------------- setup ------------------------------------------------------
__global__ void k_nop() {}

__global__ void k_prep(const float* __restrict__ wr_w, const float* __restrict__ wz_w,
                       const float* __restrict__ wij_w, const float* __restrict__ U_w,
                       const float* __restrict__ wr_b, const float* __restrict__ wz_b,
                       const float* __restrict__ wij_b) {
    int idx = blockIdx.x * 256 + threadIdx.x;   // 418*256 = 107008 exact
    const int T1 = 192 * 448, T2 = T1 + 192 * 64, T3 = T2 + 16 * 512;
    if (idx < T1) {
        int k = idx / 448, n = idx % 448;
        g_wtrz[idx] = (n < 192) ? wr_w[n * 208 + k] : wz_w[(n - 192) * 208 + k];
    } else if (idx < T2) {
        int i2 = idx - T1;
        int k = i2 / 64, n = i2 % 64;
        g_wt2[i2] = U_w[n * 192 + k];
    } else if (idx < T3) {
        int i2 = idx - T2;
        int c = i2 / 512, n = i2 % 512;
        g_wx[i2] = (n < 192)   ? wr_w[n * 208 + 192 + c]
                 : (n < 448) ? wz_w[(n - 192) * 208 + 192 + c]
                             : wij_w[(n - 448) * 16 + c];
    } else {
        int n = idx - T3;
        g_bias[n] = (n < 192) ? wr_b[n] : (n < 448) ? wz_b[n - 192] : wij_b[n - 448];
    }
    if (idx < 64) g_flag[idx] = 0;
}

// g_s[cell][row][col] = sum_c x[row][c] * Wx[c][col] + bias[col]
__global__ __launch_bounds__(256) void k_sxz(const float* __restrict__ inputs) {
    __shared__ float sW[16 * 512];
    __shared__ float sb[512];
    __shared__ float sx[64 * 16];
    const int cell = blockIdx.x;
    const int tid = threadIdx.x;
    for (int i = tid; i < 8192; i += 256) sW[i] = g_wx[i];
    for (int i = tid; i < 512; i += 256) sb[i] = g_bias[i];
    for (int i = tid; i < 1024; i += 256) sx[i] = inputs[(size_t)i * 4096 + cell];
    __syncthreads();
    const int ryq = tid >> 4, cx = tid & 15;
    const int row0 = ryq * 4;
    float* outp = g_s + (size_t)cell * 64 * 512;
#pragma unroll 1
    for (int p = 0; p < 4; ++p) {
        const int col0 = p * 128 + cx * 8;
        unsigned long long acc[4][4];
        {
            float4 b0 = *reinterpret_cast<const float4*>(&sb[col0]);
            float4 b1 = *reinterpret_cast<const float4*>(&sb[col0 + 4]);
            unsigned long long p0 = f2_pack(b0.x, b0.y), p1 = f2_pack(b0.z, b0.w);
            unsigned long long p2 = f2_pack(b1.x, b1.y), p3 = f2_pack(b1.z, b1.w);
#pragma unroll
            for (int i = 0; i < 4; ++i) {
                acc[i][0] = p0; acc[i][1] = p1; acc[i][2] = p2; acc[i][3] = p3;
            }
        }
#pragma unroll
        for (int k = 0; k < 16; k += 4) {
            float4 a[4];
#pragma unroll
            for (int i = 0; i < 4; ++i)
                a[i] = *reinterpret_cast<const float4*>(&sx[(row0 + i) * 16 + k]);
#pragma unroll
            for (int kk = 0; kk < 4; ++kk) {
                ulonglong2 w0 = *reinterpret_cast<const ulonglong2*>(sW + (k + kk) * 512 + col0);
                ulonglong2 w1 = *reinterpret_cast<const ulonglong2*>(sW + (k + kk) * 512 + col0 + 4);
#pragma unroll
                for (int i = 0; i < 4; ++i) {
                    unsigned long long d = f2_dup(reinterpret_cast<const float*>(&a[i])[kk]);
                    acc[i][0] = f2_fma(d, w0.x, acc[i][0]);
                    acc[i][1] = f2_fma(d, w0.y, acc[i][1]);
                    acc[i][2] = f2_fma(d, w1.x, acc[i][2]);
                    acc[i][3] = f2_fma(d, w1.y, acc[i][3]);
                }
            }
        }
#pragma unroll
        for (int i = 0; i < 4; ++i) {
            float2 u0 = f2_unpack(acc[i][0]), u1 = f2_unpack(acc[i][1]);
            float2 u2 = f2_unpack(acc[i][2]), u3 = f2_unpack(acc[i][3]);
            float4 o0 = {u0.x, u0.y, u1.x, u1.y};
            float4 o1 = {u2.x, u2.y, u3.x, u3.y};
            *reinterpret_cast<float4*>(&outp[(row0 + i) * 512 + col0]) = o0;
            *reinterpret_cast<float4*>(&outp[(row0 + i) * 512 + col0 + 4]) = o1;
        }
    }
}

// ---- GEMM1 K=64 segment: 8 rows x 4 cols, W lanes line-contiguous ----------
__device__ __forceinline__ void gemm1_seg(const float* __restrict__ A, int row0,
                                          const float* __restrict__ Wc,
                                          unsigned long long acc[8][2]) {
#pragma unroll 4
    for (int k = 0; k < 64; k += 4) {
        ulonglong2 w[4];
#pragma unroll
        for (int kk = 0; kk < 4; ++kk)
            w[kk] = *reinterpret_cast<const ulonglong2*>(Wc + (k + kk) * 448);
#pragma unroll
        for (int half = 0; half < 2; ++half) {
            float4 a[4];
#pragma unroll
            for (int i = 0; i < 4; ++i)
                a[i] = *reinterpret_cast<const float4*>(
                    &A[(row0 + half * 4 + i) * 64 + k]);
#pragma unroll
            for (int kk = 0; kk < 4; ++kk) {
#pragma unroll
                for (int i = 0; i < 4; ++i) {
                    unsigned long long d =
                        f2_dup(reinterpret_cast<const float*>(&a[i])[kk]);
                    acc[half * 4 + i][0] = f2_fma(d, w[kk].x, acc[half * 4 + i][0]);
                    acc[half * 4 + i][1] = f2_fma(d, w[kk].y, acc[half * 4 + i][1]);
                }
            }
        }
    }
}

// ---- GEMM2: 2 rows (ty, ty+32) x 4 cols, K=192 over sRR --------------------
__device__ __forceinline__ void gemm2_seg(const float* __restrict__ A,
                                          const float* __restrict__ Wc, int ty,
                                          unsigned long long acc0[2],
                                          unsigned long long acc1[2]) {
#pragma unroll 4
    for (int k = 0; k < 192; k += 4) {
        float4 a0 = *reinterpret_cast<const float4*>(&A[ty * 192 + k]);
        float4 a1 = *reinterpret_cast<const float4*>(&A[(ty + 32) * 192 + k]);
#pragma unroll
        for (int kk = 0; kk < 4; ++kk) {
            ulonglong2 w = *reinterpret_cast<const ulonglong2*>(Wc + (k + kk) * 64);
            unsigned long long d0 = f2_dup(reinterpret_cast<const float*>(&a0)[kk]);
            unsigned long long d1 = f2_dup(reinterpret_cast<const float*>(&a1)[kk]);
            acc0[0] = f2_fma(d0, w.x, acc0[0]);
            acc1[0] = f2_fma(d0, w.y, acc1[0]);
            acc0[1] = f2_fma(d1, w.x, acc0[1]);
            acc1[1] = f2_fma(d1, w.y, acc1[1]);
        }
    }
}

// ---------------- wavefront kernel -------------------------------------------
__global__ __launch_bounds__(896, 1) void k_wave(float* __restrict__ out) {
    extern __shared__ float sm[];
    float* sHT = sm;
    float* sRR = sm + cfg::SM_RR;
    float* sZ  = sm + cfg::SM_Z;

    const int tid = threadIdx.x;
    const int cg = tid % 112, rg = tid / 112;   // col-fast mapping
    const int col0 = cg * 4;                    // 4 cols per thread
    const int row0 = rg * 8;                    // 8 rows per thread
    const int blk = col0 >> 6, off = col0 & 63;
    const int tx2 = tid & 15, ty2 = tid >> 4;   // GEMM2 (tid < 512)
    const int lc0 = 4 * tx2;
    const int r = blockIdx.x;

    for (int i = tid; i < 3 * 4096; i += 896) sm[i] = 0.f;
    __syncthreads();

#pragma unroll 1
    for (int l = 0; l < 64; ++l) {
        float* sHL = sm + ((l & 1) ? 8192 : 4096);
        float* sHD = sm + ((l & 1) ? 4096 : 8192);

        if (r > 0) {
            if (tid == 0) {
                while (ld_acq(&g_flag[r - 1]) < l + 1) __nanosleep(64);
            }
            __syncthreads();
            const float4* src =
                reinterpret_cast<const float4*>(g_h + (size_t)(l * 64 + (r - 1)) * 4096);
            float4* dst = reinterpret_cast<float4*>(sHL);
            for (int i = tid; i < 1024; i += 896) dst[i] = src[i];
            __syncthreads();
        }

        const size_t cellbase = (size_t)(l * 64 + r) * 64 * 512;

        // ---- GEMM1: [HT|HL|HD] @ Wrz + g_s, all 448 cols in one pass ----
        {
            unsigned long long acc[8][2];
            const float* sp = g_s + cellbase + col0;
#pragma unroll
            for (int i = 0; i < 8; ++i) {
                float4 s = *reinterpret_cast<const float4*>(sp + (row0 + i) * 512);
                acc[i][0] = f2_pack(s.x, s.y);
                acc[i][1] = f2_pack(s.z, s.w);
            }
            const float* Wc = g_wtrz + col0;
            gemm1_seg(sHT, row0, Wc, acc);
            gemm1_seg(sHL, row0, Wc + 64 * 448, acc);
            gemm1_seg(sHD, row0, Wc + 128 * 448, acc);

            if (blk < 3) {
                const float* HU = (blk == 0) ? sHL : (blk == 1) ? sHT : sHD;
#pragma unroll
                for (int i = 0; i < 8; ++i) {
                    int row = row0 + i;
                    float2 u0 = f2_unpack(acc[i][0]), u1 = f2_unpack(acc[i][1]);
                    float4 hu = *reinterpret_cast<const float4*>(&HU[row * 64 + off]);
                    float4 o = {hu.x * fsigmoid(u0.x), hu.y * fsigmoid(u0.y),
                                hu.z * fsigmoid(u1.x), hu.w * fsigmoid(u1.y)};
                    *reinterpret_cast<float4*>(&sRR[row * 192 + blk * 64 + off]) = o;
                }
            } else {
#pragma unroll
                for (int i = 0; i < 8; ++i) {
                    int row = row0 + i;
                    float2 u0 = f2_unpack(acc[i][0]), u1 = f2_unpack(acc[i][1]);
                    float4 o = {u0.x, u0.y, u1.x, u1.y};
                    *reinterpret_cast<float4*>(&sZ[row * 256 + (blk - 3) * 64 + off]) = o;
                }
            }
        }
        __syncthreads();

        // ---- GEMM2 (tid < 512): rr*hu @ U_w^T + g_s[:,448:], gates, h ----
        if (tid < 512) {
            unsigned long long acc0[2], acc1[2];
#pragma unroll
            for (int i = 0; i < 2; ++i) {
                int row = ty2 + 32 * i;
                float4 s = *reinterpret_cast<const float4*>(
                    g_s + cellbase + (size_t)row * 512 + 448 + lc0);
                acc0[i] = f2_pack(s.x, s.y);
                acc1[i] = f2_pack(s.z, s.w);
            }
            gemm2_seg(sRR, g_wt2 + lc0, ty2, acc0, acc1);

#pragma unroll
            for (int i = 0; i < 2; ++i) {
                int row = ty2 + 32 * i;
                float2 v01 = f2_unpack(acc0[i]), v23 = f2_unpack(acc1[i]);
                float hn[4] = {tanhf(v01.x), tanhf(v01.y), tanhf(v23.x), tanhf(v23.y)};
                const float* zr = sZ + row * 256 + lc0;
                float4 zi4 = *reinterpret_cast<const float4*>(zr);
                float4 zl4 = *reinterpret_cast<const float4*>(zr + 64);
                float4 zt4 = *reinterpret_cast<const float4*>(zr + 128);
                float4 zd4 = *reinterpret_cast<const float4*>(zr + 192);
                float4 hl4 = *reinterpret_cast<const float4*>(&sHL[row * 64 + lc0]);
                float4 ht4 = *reinterpret_cast<const float4*>(&sHT[row * 64 + lc0]);
                float4 hd4 = *reinterpret_cast<const float4*>(&sHD[row * 64 + lc0]);
                float zi[4] = {zi4.x, zi4.y, zi4.z, zi4.w};
                float zl[4] = {zl4.x, zl4.y, zl4.z, zl4.w};
                float zt[4] = {zt4.x, zt4.y, zt4.z, zt4.w};
                float zd[4] = {zd4.x, zd4.y, zd4.z, zd4.w};
                float hl[4] = {hl4.x, hl4.y, hl4.z, hl4.w};
                float ht[4] = {ht4.x, ht4.y, ht4.z, ht4.w};
                float hd[4] = {hd4.x, hd4.y, hd4.z, hd4.w};
                float h[4];
#pragma unroll
                for (int j = 0; j < 4; ++j) {
                    float m = fmaxf(fmaxf(zi[j], zl[j]), fmaxf(zt[j], zd[j]));
                    float ei = __expf(zi[j] - m), el = __expf(zl[j] - m);
                    float et = __expf(zt[j] - m), ed = __expf(zd[j] - m);
                    float inv = 1.f / (ei + el + et + ed);
                    h[j] = (el * hl[j] + et * ht[j] + ed * hd[j] + ei * hn[j]) * inv;
                }
                float4 h4 = {h[0], h[1], h[2], h[3]};
                *reinterpret_cast<float4*>(&sHT[row * 64 + lc0]) = h4;
                if (r < 63)
                    *reinterpret_cast<float4*>(
                        g_h + ((size_t)(l * 64 + r) * 64 + row) * 64 + lc0) = h4;
                if (l == 63 && r == 63)
                    *reinterpret_cast<float4*>(out + row * 64 + lc0) = h4;
            }
        }
        __threadfence();
        __syncthreads();
        if (tid == 0) st_rel(&g_flag[r], l + 1);
    }
}

// ---------------- launch ------------------------------------------------------
extern "C" void kernel_launch(void* const* d_in, const int* in_sizes, int n_in,
                              void* d_out, int out_size) {
    const float* inputs = (const float*)d_in[0];
    const float* wr_w = (const float*)d_in[1];
    const float* wr_b = (const float*)d_in[2];
    const float* wz_w = (const float*)d_in[3];
    const float* wz_b = (const float*)d_in[4];
    const float* wij_w = (const float*)d_in[5];
    const float* wij_b = (const float*)d_in[6];
    const float* U_w = (const float*)d_in[7];
    float* out = (float*)d_out;

    cudaFuncSetAttribute(k_wave, cudaFuncAttributeMaxDynamicSharedMemorySize,
                         cfg::SM_BYTES);

    k_nop<<<1, 1>>>();   // pad launch sequence (ncu -s alignment)
    k_prep<<<418, 256>>>(wr_w, wz_w, wij_w, U_w, wr_b, wz_b, wij_b);
    k_sxz<<<4096, 256>>>(inputs);
    k_wave<<<64, 896, cfg::SM_BYTES>>>(out);
}

// round 7
// speedup vs baseline: 2.7441x; 2.1149x over previous
#include <cuda_runtime.h>

// SpatialGRU wavefront v4: batch-split 2x -> 128 persistent CTAs x 448 threads.
// CTA (half, r) computes batch rows half*32..+31 of column r. The two halves
// are fully independent wavefronts (batch separability of the recurrence).

namespace cfg {
constexpr int SM_HT = 0;       // 32x64
constexpr int SM_P0 = 2048;    // 32x64 ping
constexpr int SM_P1 = 4096;    // 32x64 pong
constexpr int SM_RR = 6144;    // 32x192
constexpr int SM_Z  = 12288;   // 32x256
constexpr int SM_FLOATS = 20480;
constexpr int SM_BYTES = SM_FLOATS * 4;   // 81920
}

__device__ __align__(16) float g_s[(size_t)4096 * 64 * 512];   // [cell][b][512]
__device__ __align__(16) float g_h[(size_t)4096 * 64 * 64];    // [cell][b][u]
__device__ __align__(16) float g_wtrz[192 * 448];              // [k][n]
__device__ __align__(16) float g_wt2[192 * 64];                // [k][n] (U_w^T)
__device__ __align__(16) float g_wx[16 * 512];                 // [c][n]
__device__ __align__(16) float g_bias[512];
__device__ int g_flag[128];                                    // [half*64 + r]

// ---------------- helpers ----------------------------------------------------
__device__ __forceinline__ unsigned long long f2_pack(float lo, float hi) {
    unsigned long long d;
    asm("mov.b64 %0, {%1, %2};" : "=l"(d) : "f"(lo), "f"(hi));
    return d;
}
__device__ __forceinline__ unsigned long long f2_dup(float a) {
    unsigned long long d;
    asm("mov.b64 %0, {%1, %1};" : "=l"(d) : "f"(a));
    return d;
}
__device__ __forceinline__ float2 f2_unpack(unsigned long long v) {
    float2 r;
    asm("mov.b64 {%0, %1}, %2;" : "=f"(r.x), "=f"(r.y) : "l"(v));
    return r;
}
__device__ __forceinline__ unsigned long long f2_fma(unsigned long long a,
                                                     unsigned long long b,
                                                     unsigned long long c) {
    unsigned long long d;
    asm("fma.rn.f32x2 %0, %1, %2, %3;" : "=l"(d) : "l"(a), "l"(b), "l"(c));
    return d;
}
__device__ __forceinline__ int ld_acq(const int* p) {
    int v;
    asm volatile("ld.global.acquire.gpu.b32 %0, [%1];" : "=r"(v) : "l"(p) : "memory");
    return v;
}
__device__ __forceinline__ void st_rel(int* p, int v) {
    asm volatile("st.global.release.gpu.b32 [%0], %1;" :: "l"(p), "r"(v) : "memory");
}
__device__ __forceinline__ float fsigmoid(float x) { return 1.f / (1.f + __expf(-x)); }

// ---------------- setup ------------------------------------------------------
__global__ void k_nop() {}

__global__ void k_prep(const float* __restrict__ wr_w, const float* __restrict__ wz_w,
                       const float* __restrict__ wij_w, const float* __restrict__ U_w,
                       const float* __restrict__ wr_b, const float* __restrict__ wz_b,
                       const float* __restrict__ wij_b) {
    int idx = blockIdx.x * 256 + threadIdx.x;   // 418*256 = 107008 exact
    const int T1 = 192 * 448, T2 = T1 + 192 * 64, T3 = T2 + 16 * 512;
    if (idx < T1) {
        int k = idx / 448, n = idx % 448;
        g_wtrz[idx] = (n < 192) ? wr_w[n * 208 + k] : wz_w[(n - 192) * 208 + k];
    } else if (idx < T2) {
        int i2 = idx - T1;
        int k = i2 / 64, n = i2 % 64;
        g_wt2[i2] = U_w[n * 192 + k];
    } else if (idx < T3) {
        int i2 = idx - T2;
        int c = i2 / 512, n = i2 % 512;
        g_wx[i2] = (n < 192)   ? wr_w[n * 208 + 192 + c]
                 : (n < 448) ? wz_w[(n - 192) * 208 + 192 + c]
                             : wij_w[(n - 448) * 16 + c];
    } else {
        int n = idx - T3;
        g_bias[n] = (n < 192) ? wr_b[n] : (n < 448) ? wz_b[n - 192] : wij_b[n - 448];
    }
    if (idx < 128) g_flag[idx] = 0;
}

// g_s[cell][row][col] = sum_c x[row][c] * Wx[c][col] + bias[col]
__global__ __launch_bounds__(256) void k_sxz(const float* __restrict__ inputs) {
    __shared__ float sW[16 * 512];
    __shared__ float sb[512];
    __shared__ float sx[64 * 16];
    const int cell = blockIdx.x;
    const int tid = threadIdx.x;
    for (int i = tid; i < 8192; i += 256) sW[i] = g_wx[i];
    for (int i = tid; i < 512; i += 256) sb[i] = g_bias[i];
    for (int i = tid; i < 1024; i += 256) sx[i] = inputs[(size_t)i * 4096 + cell];
    __syncthreads();
    const int ryq = tid >> 4, cx = tid & 15;
    const int row0 = ryq * 4;
    float* outp = g_s + (size_t)cell * 64 * 512;
#pragma unroll 1
    for (int p = 0; p < 4; ++p) {
        const int col0 = p * 128 + cx * 8;
        unsigned long long acc[4][4];
        {
            float4 b0 = *reinterpret_cast<const float4*>(&sb[col0]);
            float4 b1 = *reinterpret_cast<const float4*>(&sb[col0 + 4]);
            unsigned long long p0 = f2_pack(b0.x, b0.y), p1 = f2_pack(b0.z, b0.w);
            unsigned long long p2 = f2_pack(b1.x, b1.y), p3 = f2_pack(b1.z, b1.w);
#pragma unroll
            for (int i = 0; i < 4; ++i) {
                acc[i][0] = p0; acc[i][1] = p1; acc[i][2] = p2; acc[i][3] = p3;
            }
        }
#pragma unroll
        for (int k = 0; k < 16; k += 4) {
            float4 a[4];
#pragma unroll
            for (int i = 0; i < 4; ++i)
                a[i] = *reinterpret_cast<const float4*>(&sx[(row0 + i) * 16 + k]);
#pragma unroll
            for (int kk = 0; kk < 4; ++kk) {
                ulonglong2 w0 = *reinterpret_cast<const ulonglong2*>(sW + (k + kk) * 512 + col0);
                ulonglong2 w1 = *reinterpret_cast<const ulonglong2*>(sW + (k + kk) * 512 + col0 + 4);
#pragma unroll
                for (int i = 0; i < 4; ++i) {
                    unsigned long long d = f2_dup(reinterpret_cast<const float*>(&a[i])[kk]);
                    acc[i][0] = f2_fma(d, w0.x, acc[i][0]);
                    acc[i][1] = f2_fma(d, w0.y, acc[i][1]);
                    acc[i][2] = f2_fma(d, w1.x, acc[i][2]);
                    acc[i][3] = f2_fma(d, w1.y, acc[i][3]);
                }
            }
        }
#pragma unroll
        for (int i = 0; i < 4; ++i) {
            float2 u0 = f2_unpack(acc[i][0]), u1 = f2_unpack(acc[i][1]);
            float2 u2 = f2_unpack(acc[i][2]), u3 = f2_unpack(acc[i][3]);
            float4 o0 = {u0.x, u0.y, u1.x, u1.y};
            float4 o1 = {u2.x, u2.y, u3.x, u3.y};
            *reinterpret_cast<float4*>(&outp[(row0 + i) * 512 + col0]) = o0;
            *reinterpret_cast<float4*>(&outp[(row0 + i) * 512 + col0 + 4]) = o1;
        }
    }
}

// ---- GEMM1 K=64 segment: 8 rows x 4 cols, W lanes line-contiguous ----------
__device__ __forceinline__ void gemm1_seg(const float* __restrict__ A, int row0,
                                          const float* __restrict__ Wc,
                                          unsigned long long acc[8][2]) {
#pragma unroll 4
    for (int k = 0; k < 64; k += 4) {
        ulonglong2 w[4];
#pragma unroll
        for (int kk = 0; kk < 4; ++kk)
            w[kk] = *reinterpret_cast<const ulonglong2*>(Wc + (k + kk) * 448);
#pragma unroll
        for (int half = 0; half < 2; ++half) {
            float4 a[4];
#pragma unroll
            for (int i = 0; i < 4; ++i)
                a[i] = *reinterpret_cast<const float4*>(
                    &A[(row0 + half * 4 + i) * 64 + k]);
#pragma unroll
            for (int kk = 0; kk < 4; ++kk) {
#pragma unroll
                for (int i = 0; i < 4; ++i) {
                    unsigned long long d =
                        f2_dup(reinterpret_cast<const float*>(&a[i])[kk]);
                    acc[half * 4 + i][0] = f2_fma(d, w[kk].x, acc[half * 4 + i][0]);
                    acc[half * 4 + i][1] = f2_fma(d, w[kk].y, acc[half * 4 + i][1]);
                }
            }
        }
    }
}

// ---- GEMM2: 2 rows (ty, ty+16) x 4 cols, K=192 over sRR --------------------
__device__ __forceinline__ void gemm2_seg(const float* __restrict__ A,
                                          const float* __restrict__ Wc, int ty,
                                          unsigned long long acc0[2],
                                          unsigned long long acc1[2]) {
#pragma unroll 4
    for (int k = 0; k < 192; k += 4) {
        float4 a0 = *reinterpret_cast<const float4*>(&A[ty * 192 + k]);
        float4 a1 = *reinterpret_cast<const float4*>(&A[(ty + 16) * 192 + k]);
#pragma unroll
        for (int kk = 0; kk < 4; ++kk) {
            ulonglong2 w = *reinterpret_cast<const ulonglong2*>(Wc + (k + kk) * 64);
            unsigned long long d0 = f2_dup(reinterpret_cast<const float*>(&a0)[kk]);
            unsigned long long d1 = f2_dup(reinterpret_cast<const float*>(&a1)[kk]);
            acc0[0] = f2_fma(d0, w.x, acc0[0]);
            acc1[0] = f2_fma(d0, w.y, acc1[0]);
            acc0[1] = f2_fma(d1, w.x, acc0[1]);
            acc1[1] = f2_fma(d1, w.y, acc1[1]);
        }
    }
}

// ---------------- wavefront kernel -------------------------------------------
__global__ __launch_bounds__(448, 1) void k_wave(float* __restrict__ out) {
    extern __shared__ float sm[];
    float* sHT = sm + cfg::SM_HT;
    float* sRR = sm + cfg::SM_RR;
    float* sZ  = sm + cfg::SM_Z;

    const int tid = threadIdx.x;
    const int bid = blockIdx.x;
    const int r = bid & 63, half = bid >> 6;
    const int rb0 = half * 32;                  // global batch-row base
    const int cg = tid % 112, rg = tid / 112;   // GEMM1: col-fast mapping
    const int col0 = cg * 4;                    // 4 cols/thread
    const int row0 = rg * 8;                    // 8 rows/thread (of 32)
    const int blk = col0 >> 6, off = col0 & 63;
    const int tx2 = tid & 15, ty2 = tid >> 4;   // GEMM2 (tid < 256)
    const int lc0 = 4 * tx2;

    for (int i = tid; i < 3 * 2048; i += 448) sm[i] = 0.f;   // HT, P0, P1 = 0
    __syncthreads();

#pragma unroll 1
    for (int l = 0; l < 64; ++l) {
        float* sHL = sm + ((l & 1) ? cfg::SM_P1 : cfg::SM_P0);
        float* sHD = sm + ((l & 1) ? cfg::SM_P0 : cfg::SM_P1);

        const size_t cellbase = (size_t)(l * 64 + r) * 64 * 512;

        // prefetch g_s accumulator init (DRAM-cold) before the dependency wait
        float4 sv[8];
        {
            const float* sp = g_s + cellbase + (size_t)rb0 * 512 + col0;
#pragma unroll
            for (int i = 0; i < 8; ++i)
                sv[i] = *reinterpret_cast<const float4*>(sp + (row0 + i) * 512);
        }

        if (r > 0) {
            if (tid == 0) {
                while (ld_acq(&g_flag[half * 64 + r - 1]) < l + 1) __nanosleep(32);
            }
            __syncthreads();
            const float4* src = reinterpret_cast<const float4*>(
                g_h + ((size_t)(l * 64 + (r - 1)) * 64 + rb0) * 64);
            float4* dst = reinterpret_cast<float4*>(sHL);
            for (int i = tid; i < 512; i += 448) dst[i] = src[i];
            __syncthreads();
        }

        // ---- GEMM1: [HT|HL|HD](32x192) @ Wrz + s, all 448 cols ----
        {
            unsigned long long acc[8][2];
#pragma unroll
            for (int i = 0; i < 8; ++i) {
                acc[i][0] = f2_pack(sv[i].x, sv[i].y);
                acc[i][1] = f2_pack(sv[i].z, sv[i].w);
            }
            const float* Wc = g_wtrz + col0;
            gemm1_seg(sHT, row0, Wc, acc);
            gemm1_seg(sHL, row0, Wc + 64 * 448, acc);
            gemm1_seg(sHD, row0, Wc + 128 * 448, acc);

            if (blk < 3) {
                const float* HU = (blk == 0) ? sHL : (blk == 1) ? sHT : sHD;
#pragma unroll
                for (int i = 0; i < 8; ++i) {
                    int row = row0 + i;
                    float2 u0 = f2_unpack(acc[i][0]), u1 = f2_unpack(acc[i][1]);
                    float4 hu = *reinterpret_cast<const float4*>(&HU[row * 64 + off]);
                    float4 o = {hu.x * fsigmoid(u0.x), hu.y * fsigmoid(u0.y),
                                hu.z * fsigmoid(u1.x), hu.w * fsigmoid(u1.y)};
                    *reinterpret_cast<float4*>(&sRR[row * 192 + blk * 64 + off]) = o;
                }
            } else {
#pragma unroll
                for (int i = 0; i < 8; ++i) {
                    int row = row0 + i;
                    float2 u0 = f2_unpack(acc[i][0]), u1 = f2_unpack(acc[i][1]);
                    float4 o = {u0.x, u0.y, u1.x, u1.y};
                    *reinterpret_cast<float4*>(&sZ[row * 256 + (blk - 3) * 64 + off]) = o;
                }
            }
        }
        __syncthreads();

        // ---- GEMM2 (tid < 256): rr*hu @ U_w^T + s[:,448:], gates, h ----
        if (tid < 256) {
            unsigned long long acc0[2], acc1[2];
#pragma unroll
            for (int i = 0; i < 2; ++i) {
                int row = ty2 + 16 * i;
                float4 s = *reinterpret_cast<const float4*>(
                    g_s + cellbase + (size_t)(rb0 + row) * 512 + 448 + lc0);
                acc0[i] = f2_pack(s.x, s.y);
                acc1[i] = f2_pack(s.z, s.w);
            }
            gemm2_seg(sRR, g_wt2 + lc0, ty2, acc0, acc1);

#pragma unroll
            for (int i = 0; i < 2; ++i) {
                int row = ty2 + 16 * i;
                float2 v01 = f2_unpack(acc0[i]), v23 = f2_unpack(acc1[i]);
                float hn[4] = {tanhf(v01.x), tanhf(v01.y), tanhf(v23.x), tanhf(v23.y)};
                const float* zr = sZ + row * 256 + lc0;
                float4 zi4 = *reinterpret_cast<const float4*>(zr);
                float4 zl4 = *reinterpret_cast<const float4*>(zr + 64);
                float4 zt4 = *reinterpret_cast<const float4*>(zr + 128);
                float4 zd4 = *reinterpret_cast<const float4*>(zr + 192);
                float4 hl4 = *reinterpret_cast<const float4*>(&sHL[row * 64 + lc0]);
                float4 ht4 = *reinterpret_cast<const float4*>(&sHT[row * 64 + lc0]);
                float4 hd4 = *reinterpret_cast<const float4*>(&sHD[row * 64 + lc0]);
                float zi[4] = {zi4.x, zi4.y, zi4.z, zi4.w};
                float zl[4] = {zl4.x, zl4.y, zl4.z, zl4.w};
                float zt[4] = {zt4.x, zt4.y, zt4.z, zt4.w};
                float zd[4] = {zd4.x, zd4.y, zd4.z, zd4.w};
                float hl[4] = {hl4.x, hl4.y, hl4.z, hl4.w};
                float ht[4] = {ht4.x, ht4.y, ht4.z, ht4.w};
                float hd[4] = {hd4.x, hd4.y, hd4.z, hd4.w};
                float h[4];
#pragma unroll
                for (int j = 0; j < 4; ++j) {
                    float m = fmaxf(fmaxf(zi[j], zl[j]), fmaxf(zt[j], zd[j]));
                    float ei = __expf(zi[j] - m), el = __expf(zl[j] - m);
                    float et = __expf(zt[j] - m), ed = __expf(zd[j] - m);
                    float inv = 1.f / (ei + el + et + ed);
                    h[j] = (el * hl[j] + et * ht[j] + ed * hd[j] + ei * hn[j]) * inv;
                }
                float4 h4 = {h[0], h[1], h[2], h[3]};
                *reinterpret_cast<float4*>(&sHT[row * 64 + lc0]) = h4;
                if (r < 63)
                    *reinterpret_cast<float4*>(
                        g_h + ((size_t)(l * 64 + r) * 64 + rb0 + row) * 64 + lc0) = h4;
                if (l == 63 && r == 63)
                    *reinterpret_cast<float4*>(out + (rb0 + row) * 64 + lc0) = h4;
            }
        }
        __syncthreads();   // orders all stores before the release below
        if (tid == 0) st_rel(&g_flag[half * 64 + r], l + 1);
    }
}

// ---------------- launch ------------------------------------------------------
extern "C" void kernel_launch(void* const* d_in, const int* in_sizes, int n_in,
                              void* d_out, int out_size) {
    const float* inputs = (const float*)d_in[0];
    const float* wr_w = (const float*)d_in[1];
    const float* wr_b = (const float*)d_in[2];
    const float* wz_w = (const float*)d_in[3];
    const float* wz_b = (const float*)d_in[4];
    const float* wij_w = (const float*)d_in[5];
    const float* wij_b = (const float*)d_in[6];
    const float* U_w = (const float*)d_in[7];
    float* out = (float*)d_out;

    cudaFuncSetAttribute(k_wave, cudaFuncAttributeMaxDynamicSharedMemorySize,
                         cfg::SM_BYTES);

    k_nop<<<1, 1>>>();
    k_prep<<<418, 256>>>(wr_w, wz_w, wij_w, U_w, wr_b, wz_b, wij_b);
    k_sxz<<<4096, 256>>>(inputs);
    k_wave<<<128, 448, cfg::SM_BYTES>>>(out);
}